// round 9
// baseline (speedup 1.0000x reference)
#include <cuda_runtime.h>
#include <cstdint>
#include <cstddef>

// Problem sizes
#define BB 64
#define TT 2048
#define DD 512

// Recurrence config
#define NCTA 128
#define RTHREADS 256
// SMEM: Hs [512][64] f32 (128KB) + WZ [512][4] ulonglong2 (32KB) + Red [8][128] ulonglong2 (16KB)
#define RSMEM (512*64*4 + 512*4*16 + 8*128*16)

// -------- device scratch (no allocs allowed) --------
__device__ float g_Xg[(size_t)TT * BB * DD];   // [t][b][n], includes bias
__device__ float g_Xc[(size_t)TT * BB * DD];
__device__ float g_H[2][DD * BB];              // [k][b] layout, double buffered
__device__ unsigned g_flags[NCTA * 8];         // per-CTA flag, 32B apart; zero-init, reset in-kernel

// ==================== Phase 1: x-projection GEMM ====================
// C[r, n] = seq[r, :] @ W[512: , n] + bias[n],  r = b*T + t, stored to X[t][b][n]
__global__ __launch_bounds__(256) void xproj_kernel(
    const float* __restrict__ seq, const float* __restrict__ Wg,
    const float* __restrict__ bgate, const float* __restrict__ Wc,
    const float* __restrict__ bcand)
{
    __shared__ float As[8 * 132];
    __shared__ float Bs[8 * 132];

    const int bm = blockIdx.x;            // 0..1023
    const int bn = blockIdx.y;            // 0..7 ; 0-3 gate, 4-7 cand
    const bool isCand = bn >= 4;
    const float* __restrict__ W    = isCand ? Wc : Wg;
    const float* __restrict__ bias = isCand ? bcand : bgate;
    float* __restrict__ Xout       = isCand ? g_Xc : g_Xg;
    const int n0 = (bn & 3) * 128;
    const int m0 = bm * 128;

    const int tid  = threadIdx.x;
    const int arow = tid >> 1;
    const int akk  = (tid & 1) * 4;
    const int brow = tid >> 5;
    const int bcol = (tid & 31) * 4;
    const int trow = tid >> 4;
    const int tcol = tid & 15;

    float acc[8][8];
#pragma unroll
    for (int i = 0; i < 8; i++)
#pragma unroll
        for (int j = 0; j < 8; j++) acc[i][j] = 0.0f;

    for (int k0 = 0; k0 < 512; k0 += 8) {
        float4 av = *(const float4*)(seq + (size_t)(m0 + arow) * 512 + k0 + akk);
        As[(akk + 0) * 132 + arow] = av.x;
        As[(akk + 1) * 132 + arow] = av.y;
        As[(akk + 2) * 132 + arow] = av.z;
        As[(akk + 3) * 132 + arow] = av.w;
        float4 bv = *(const float4*)(W + (size_t)(512 + k0 + brow) * 512 + n0 + bcol);
        *(float4*)(Bs + brow * 132 + bcol) = bv;
        __syncthreads();
#pragma unroll
        for (int k = 0; k < 8; k++) {
            float4 a0 = *(const float4*)(As + k * 132 + trow * 8);
            float4 a1 = *(const float4*)(As + k * 132 + trow * 8 + 4);
            float4 b0 = *(const float4*)(Bs + k * 132 + tcol * 8);
            float4 b1 = *(const float4*)(Bs + k * 132 + tcol * 8 + 4);
            float a[8] = {a0.x, a0.y, a0.z, a0.w, a1.x, a1.y, a1.z, a1.w};
            float b[8] = {b0.x, b0.y, b0.z, b0.w, b1.x, b1.y, b1.z, b1.w};
#pragma unroll
            for (int i = 0; i < 8; i++)
#pragma unroll
                for (int j = 0; j < 8; j++) acc[i][j] = fmaf(a[i], b[j], acc[i][j]);
        }
        __syncthreads();
    }

    float bb0[8];
#pragma unroll
    for (int j = 0; j < 8; j++) bb0[j] = bias[n0 + tcol * 8 + j];

#pragma unroll
    for (int i = 0; i < 8; i++) {
        int r  = m0 + trow * 8 + i;
        int bb = r >> 11;
        int tt = r & 2047;
        float* orow = Xout + ((size_t)tt * 64 + bb) * 512 + n0 + tcol * 8;
        float4 o0 = make_float4(acc[i][0] + bb0[0], acc[i][1] + bb0[1],
                                acc[i][2] + bb0[2], acc[i][3] + bb0[3]);
        float4 o1 = make_float4(acc[i][4] + bb0[4], acc[i][5] + bb0[5],
                                acc[i][6] + bb0[6], acc[i][7] + bb0[7]);
        *(float4*)(orow)     = o0;
        *(float4*)(orow + 4) = o1;
    }
}

// ==================== Phase 2: persistent recurrence ====================

__device__ __forceinline__ unsigned ld_acq(const unsigned* p) {
    unsigned v;
    asm volatile("ld.global.acquire.gpu.u32 %0, [%1];" : "=r"(v) : "l"(p) : "memory");
    return v;
}
__device__ __forceinline__ void st_rel(unsigned* p, unsigned v) {
    asm volatile("st.global.release.gpu.u32 [%0], %1;" :: "l"(p), "r"(v) : "memory");
}

// Distributed-flag grid barrier: one release store per CTA, 128 pollers each own one flag.
__device__ __forceinline__ void flag_barrier(unsigned bval, int cta, int tid) {
    __syncthreads();                               // all prior stores ordered (cumulativity)
    if (tid == 0) st_rel(&g_flags[cta * 8], bval);
    if (tid < NCTA) {
        while (ld_acq(&g_flags[tid * 8]) < bval) { }
    }
    __syncthreads();                               // broadcast observation to whole CTA
}

__global__ void __launch_bounds__(RTHREADS, 1) recur_kernel(
    const float* __restrict__ Wg, const float* __restrict__ Wc,
    float* __restrict__ out)
{
    extern __shared__ float smem[];
    float*      Hs  = smem;                              // [k=512][b=64]
    ulonglong2* WZ  = (ulonglong2*)(smem + 512 * 64);    // [k=512][c=4]: {wg splat, wc splat}
    ulonglong2* Red = WZ + 512 * 4;                      // [w=8][c*32+bp]: {accg, accc}

    const int tid   = threadIdx.x;       // 0..255
    const int cta   = blockIdx.x;
    const int nbase = cta * 4;

    // Weights: fused splat layout, loaded once.
    for (int idx = tid; idx < 4 * 512; idx += RTHREADS) {
        int c = idx & 3, k = idx >> 2;
        float wg = Wg[(size_t)k * 512 + nbase + c];   // h-part: rows 0..511
        float wc = Wc[(size_t)k * 512 + nbase + c];
        unsigned gb = __float_as_uint(wg), cb = __float_as_uint(wc);
        ulonglong2 v;
        v.x = ((unsigned long long)gb << 32) | gb;
        v.y = ((unsigned long long)cb << 32) | cb;
        WZ[k * 4 + c] = v;
    }

    // Zero H buffer 0 (h0 = 0): 32768 floats / 128 CTAs = 256 each.
    g_H[0][cta * 256 + tid] = 0.0f;

    unsigned bval = 1;
    flag_barrier(bval, cta, tid); bval++;

    const int bp  = tid & 31;
    const int wid = tid >> 5;            // 0..7 : k-slice owner, covers ALL 4 cols
    const int kbase = wid * 64;
    // Epilogue mapping (tid < 128): (jp, bp) combo
    const int jp_e = tid >> 5;           // 0..3 when tid<128
    const int b0_e = bp * 2, b1_e = b0_e + 1;
    const int n_e  = nbase + jp_e;

    for (int t = 0; t < TT; t++) {
        // Prefetch per-step x-projections early (independent of H exchange).
        float xg0 = 0.f, xg1 = 0.f, xc0 = 0.f, xc1 = 0.f;
        if (tid < 128) {
            const size_t xoff = (size_t)t * 64 * 512;
            xg0 = g_Xg[xoff + (size_t)b0_e * 512 + n_e];
            xg1 = g_Xg[xoff + (size_t)b1_e * 512 + n_e];
            xc0 = g_Xc[xoff + (size_t)b0_e * 512 + n_e];
            xc1 = g_Xc[xoff + (size_t)b1_e * 512 + n_e];
        }

        // Stage full H (other CTAs wrote it) — MUST bypass L1 (.cg).
        const float4* Hg4 = (const float4*)g_H[t & 1];
        float4* Hs4 = (float4*)Hs;
#pragma unroll 8
        for (int f = tid; f < 8192; f += RTHREADS) {
            Hs4[f] = __ldcg(Hg4 + f);
        }
        __syncthreads();

        // Dot: warp owns k-slice [kbase, kbase+64), covers all 4 columns x {gate,cand}.
        // Each h2 read (256B crossbar) amortized over 8 FFMA2.
        unsigned long long ag0 = 0, ag1 = 0, ag2 = 0, ag3 = 0;
        unsigned long long ac0 = 0, ac1 = 0, ac2 = 0, ac3 = 0;
        const unsigned long long* H2 = (const unsigned long long*)Hs;
#pragma unroll 4
        for (int k = 0; k < 64; k++) {
            unsigned long long h2 = H2[(kbase + k) * 32 + bp];
            const ulonglong2* wk = WZ + (kbase + k) * 4;
            ulonglong2 w0 = wk[0], w1 = wk[1], w2 = wk[2], w3 = wk[3];
            asm("fma.rn.f32x2 %0, %1, %2, %0;" : "+l"(ag0) : "l"(h2), "l"(w0.x));
            asm("fma.rn.f32x2 %0, %1, %2, %0;" : "+l"(ac0) : "l"(h2), "l"(w0.y));
            asm("fma.rn.f32x2 %0, %1, %2, %0;" : "+l"(ag1) : "l"(h2), "l"(w1.x));
            asm("fma.rn.f32x2 %0, %1, %2, %0;" : "+l"(ac1) : "l"(h2), "l"(w1.y));
            asm("fma.rn.f32x2 %0, %1, %2, %0;" : "+l"(ag2) : "l"(h2), "l"(w2.x));
            asm("fma.rn.f32x2 %0, %1, %2, %0;" : "+l"(ac2) : "l"(h2), "l"(w2.y));
            asm("fma.rn.f32x2 %0, %1, %2, %0;" : "+l"(ag3) : "l"(h2), "l"(w3.x));
            asm("fma.rn.f32x2 %0, %1, %2, %0;" : "+l"(ac3) : "l"(h2), "l"(w3.y));
        }

        // Deposit partials: [w][c*32+bp]
        {
            ulonglong2 r;
            r.x = ag0; r.y = ac0; Red[wid * 128 +  0 + bp] = r;
            r.x = ag1; r.y = ac1; Red[wid * 128 + 32 + bp] = r;
            r.x = ag2; r.y = ac2; Red[wid * 128 + 64 + bp] = r;
            r.x = ag3; r.y = ac3; Red[wid * 128 + 96 + bp] = r;
        }
        __syncthreads();

        // Epilogue: 128 threads, one (col, b-pair) each. Deterministic w=0..7 order.
        if (tid < 128) {
            ulonglong2 v = Red[jp_e * 32 + bp];
            unsigned long long sg = v.x, sc = v.y;
#pragma unroll
            for (int w = 1; w < 8; w++) {
                ulonglong2 u = Red[w * 128 + jp_e * 32 + bp];
                asm("add.rn.f32x2 %0, %0, %1;" : "+l"(sg) : "l"(u.x));
                asm("add.rn.f32x2 %0, %0, %1;" : "+l"(sc) : "l"(u.y));
            }

            float h0 = Hs[n_e * 64 + b0_e];
            float h1 = Hs[n_e * 64 + b1_e];

            float pg0 = __uint_as_float((unsigned)(sg))       + xg0;
            float pg1 = __uint_as_float((unsigned)(sg >> 32)) + xg1;
            float pc0 = __uint_as_float((unsigned)(sc))       + xc0;
            float pc1 = __uint_as_float((unsigned)(sc >> 32)) + xc1;

            float gg0 = 1.0f / (1.0f + __expf(-pg0));
            float gg1 = 1.0f / (1.0f + __expf(-pg1));
            float cc0 = tanhf(pc0);
            float cc1 = tanhf(pc1);

            float hn0 = cc0 + gg0 * (h0 - cc0);   // g*h + (1-g)*c
            float hn1 = cc1 + gg1 * (h1 - cc1);

            float* Hn = g_H[(t + 1) & 1];
            *(float2*)(Hn + n_e * 64 + b0_e) = make_float2(hn0, hn1);

            if (t == TT - 1) {
                out[(size_t)b0_e * 512 + n_e] = hn0;
                out[(size_t)b1_e * 512 + n_e] = hn1;
            }
        }

        flag_barrier(bval, cta, tid); bval++;
    }

    // Final round + reset (CTA0 resets all flags after observing everyone).
    __syncthreads();
    if (tid == 0) st_rel(&g_flags[cta * 8], bval);
    if (cta == 0 && tid < NCTA) {
        while (ld_acq(&g_flags[tid * 8]) < bval) { }
        st_rel(&g_flags[tid * 8], 0u);
    }
}

// ==================== launch ====================
extern "C" void kernel_launch(void* const* d_in, const int* in_sizes, int n_in,
                              void* d_out, int out_size)
{
    const float* seq = (const float*)d_in[0];
    const float* Wg  = (const float*)d_in[1];
    const float* bg  = (const float*)d_in[2];
    const float* Wc  = (const float*)d_in[3];
    const float* bc  = (const float*)d_in[4];
    float* out = (float*)d_out;

    dim3 g1(1024, 8);
    xproj_kernel<<<g1, 256>>>(seq, Wg, bg, Wc, bc);

    cudaFuncSetAttribute(recur_kernel, cudaFuncAttributeMaxDynamicSharedMemorySize, RSMEM);
    recur_kernel<<<NCTA, RTHREADS, RSMEM>>>(Wg, Wc, out);
}